// round 6
// baseline (speedup 1.0000x reference)
#include <cuda_runtime.h>
#include <math.h>

#define T   256
#define NB  4
#define SQ  2048
#define HD  1024
#define NH  8
#define NC  1000
#define NR  32

#define SCALE 0.088388347648318433f  // 1/sqrt(128)

// ---------------- scratch (device globals; no allocations allowed) ----------
__device__ unsigned g_barcnt = 0;
__device__ float    g_sink;
__device__ __align__(16) float g_tmpq[NB*HD];
__device__ __align__(16) float g_q0[NB*HD];
__device__ __align__(16) float g_a[NR*HD];
__device__ __align__(16) float g_c0[NR];
__device__ __align__(16) float g_t[NR*HD];
__device__ __align__(16) float g_w[NR*SQ];
__device__ __align__(16) float g_u[NR*HD];
__device__ __align__(16) float g_wsum[NR];
__device__ __align__(16) float g_z[NR*HD];
__device__ __align__(16) float g_attn0[NB*HD];
__device__ __align__(16) float g_res[NB*HD];

__device__ __forceinline__ float warpReduceSum(float v){
    v += __shfl_xor_sync(0xffffffffu, v, 16);
    v += __shfl_xor_sync(0xffffffffu, v, 8);
    v += __shfl_xor_sync(0xffffffffu, v, 4);
    v += __shfl_xor_sync(0xffffffffu, v, 2);
    v += __shfl_xor_sync(0xffffffffu, v, 1);
    return v;
}
__device__ __forceinline__ float warpReduceMax(float v){
    v = fmaxf(v, __shfl_xor_sync(0xffffffffu, v, 16));
    v = fmaxf(v, __shfl_xor_sync(0xffffffffu, v, 8));
    v = fmaxf(v, __shfl_xor_sync(0xffffffffu, v, 4));
    v = fmaxf(v, __shfl_xor_sync(0xffffffffu, v, 2));
    v = fmaxf(v, __shfl_xor_sync(0xffffffffu, v, 1));
    return v;
}
__device__ __forceinline__ float dot4(const float4 a, const float4 b){
    return a.x*b.x + a.y*b.y + a.z*b.z + a.w*b.w;
}

// grid-wide barrier (monotonic counter; tolerant of graph replays)
__device__ __forceinline__ void gsync(){
    __threadfence();
    __syncthreads();
    if (threadIdx.x == 0){
        unsigned G = gridDim.x;
        unsigned old = atomicAdd(&g_barcnt, 1u);
        unsigned target = (old / G + 1u) * G;
        while (*(volatile unsigned*)&g_barcnt < target){
            __nanosleep(40);
        }
    }
    __syncthreads();
    __threadfence();
}

// warp-collective dot of two 1024-float vectors (global x global)
__device__ __forceinline__ float warpDot1024(const float* __restrict__ A,
                                             const float* __restrict__ B){
    const float4* a4 = (const float4*)A;
    const float4* b4 = (const float4*)B;
    int lane = threadIdx.x & 31;
    float acc = 0.f;
    #pragma unroll
    for (int k = 0; k < 8; k++)
        acc += dot4(a4[lane + 32*k], b4[lane + 32*k]);
    return warpReduceSum(acc);
}

// L2-warming sweep (accumulate to defeat DCE)
__device__ __forceinline__ void sweep(const float4* __restrict__ p, int n4,
                                      int idx, int stride, float& s){
    for (int k = idx; k < n4; k += stride){
        float4 v = p[k];
        s += v.x + v.y + v.z + v.w;
    }
}

__global__ __launch_bounds__(T)
void fused_kernel(const float* __restrict__ X,   const int*   __restrict__ mask,
                  const float* __restrict__ Wq,  const float* __restrict__ bq,
                  const float* __restrict__ Wk,  const float* __restrict__ bk,
                  const float* __restrict__ Wv,  const float* __restrict__ bv,
                  const float* __restrict__ ipw, const float* __restrict__ ipb,
                  const float* __restrict__ opw, const float* __restrict__ opb,
                  const float* __restrict__ lng, const float* __restrict__ lnb,
                  const float* __restrict__ fcw, const float* __restrict__ fcb,
                  float* __restrict__ out, float* __restrict__ wout)
{
    __shared__ __align__(16) float sh[8208];
    const int tid  = threadIdx.x;
    const int blk  = blockIdx.x;
    const int lane = tid & 31;
    const int warp = tid >> 5;
    const int G    = gridDim.x;
    const int NWd  = G*8;
    const int gw   = blk*8 + warp;
    const int P0B  = (G < 64) ? G : 64;     // blocks doing GEMV in P0/P1

    // ------- P0: zero accum; tmpq = Wq.x0 + bq  (+ prefetch X half 1) -------
    for (int i = blk*T + tid; i < NR*HD; i += G*T){ g_t[i] = 0.f; g_u[i] = 0.f; }
    if (blk < P0B){
        for (int o = blk*8 + warp; o < NB*HD; o += P0B*8){
            int b = o >> 10, i = o & (HD-1);
            float v = warpDot1024(Wq + (size_t)i*HD, X + (size_t)b*SQ*HD);
            if (lane == 0) g_tmpq[o] = v + bq[i];
        }
    } else {
        float s = 0.f;
        int idx = (blk - 64)*T + tid, stride = (G - 64)*T;
        sweep((const float4*)X, NB*SQ*HD/8, idx, stride, s);
        if (s == 123456789.0f) g_sink = s;
    }
    gsync();

    // ------- P1: q0 = wiq.tmpq + biq  (+ prefetch X half 2 & late weights) --
    if (blk < P0B){
        for (int o = blk*8 + warp; o < NB*HD; o += P0B*8){
            int b = o >> 10, i = o & (HD-1);
            float v = warpDot1024(ipw + (size_t)i*HD, g_tmpq + (size_t)b*HD);
            if (lane == 0) g_q0[o] = v + ipb[i];
        }
    } else {
        float s = 0.f;
        int idx = (blk - 64)*T + tid, stride = (G - 64)*T;
        sweep((const float4*)X + NB*SQ*HD/8, NB*SQ*HD/8, idx, stride, s);
        sweep((const float4*)Wv,  HD*HD/4, idx, stride, s);
        sweep((const float4*)opw, HD*HD/4, idx, stride, s);
        sweep((const float4*)(ipw + 2*HD*HD), HD*HD/4, idx, stride, s);
        sweep((const float4*)fcw, NC*HD/4, idx, stride, s);
        if (s == 123456789.0f) g_sink = s;
    }
    gsync();

    // ------- P2: a[r,i] = sum_j wik_h[j,i]*q0_h[j]  (128 units, no atomics) -
    for (int u = blk; u < 128; u += G){
        int r = u >> 2;
        int b = r >> 3, h = r & 7;
        int i = (u & 3)*256 + tid;
        __syncthreads();
        if (tid < 128) sh[tid] = g_q0[b*HD + h*128 + tid];
        __syncthreads();
        const float* wik = ipw + (size_t)(HD + h*128)*HD + i;
        float acc = 0.f;
        #pragma unroll 8
        for (int j = 0; j < 128; j++) acc += wik[(size_t)j*HD] * sh[j];
        g_a[r*HD + i] = acc;
    }
    gsync();

    // ------- P3: t += a.Wk (128 tiles) + c0 (units 128..131) ----------------
    for (int u = blk; u < 132; u += G){
        if (u < 128){
            int i0 = (u >> 4) * 128;
            int m0 = (u & 15) * 64;
            __syncthreads();
            for (int idx = tid; idx < NR*64; idx += T){
                int rr = idx >> 6, m = idx & 63;
                sh[idx] = g_a[rr*HD + m0 + m];
            }
            __syncthreads();
            int tx = tid & 127, ty = tid >> 7;
            float acc[16];
            #pragma unroll
            for (int q = 0; q < 16; q++) acc[q] = 0.f;
            const float* wk = Wk + (size_t)m0*HD + i0 + tx;
            for (int mm = 0; mm < 64; mm++){
                float wv = wk[(size_t)mm*HD];
                #pragma unroll
                for (int q = 0; q < 16; q++) acc[q] += sh[(ty*16+q)*64 + mm] * wv;
            }
            #pragma unroll
            for (int q = 0; q < 16; q++)
                atomicAdd(&g_t[(size_t)(ty*16+q)*HD + i0 + tx], acc[q]);
        } else {
            int r = (u - 128)*8 + warp;
            int b = r >> 3, h = r & 7;
            float acc = 0.f;
            for (int i = lane; i < HD; i += 32) acc += g_a[r*HD + i] * bk[i];
            for (int j = lane; j < 128; j += 32)
                acc += g_q0[b*HD + h*128 + j] * ipb[HD + h*128 + j];
            acc = warpReduceSum(acc);
            if (lane == 0) g_c0[r] = acc;
        }
    }
    gsync();

    // ------- P4: scores[r,key] = (t . x + c0)*SCALE (X now L2-hot) ----------
    {
        int b = blk & 3, q = blk >> 2, Q = G >> 2;
        for (int idx = tid; idx < NH*HD; idx += T)
            sh[idx] = g_t[(size_t)(b*NH)*HD + idx];
        if (tid < NH) sh[8192 + tid] = g_c0[b*NH + tid];
        __syncthreads();
        const float4* sh4 = (const float4*)sh;
        for (int key = q*8 + warp; key < SQ; key += Q*8){
            const float4* x4 = (const float4*)(X + ((size_t)b*SQ + key)*HD);
            float acc[8];
            #pragma unroll
            for (int h = 0; h < 8; h++) acc[h] = 0.f;
            #pragma unroll
            for (int c = 0; c < 8; c++){
                float4 xr = x4[c*32 + lane];
                #pragma unroll
                for (int h = 0; h < 8; h++)
                    acc[h] += dot4(xr, sh4[h*256 + c*32 + lane]);
            }
            int mk = mask[b*SQ + key];
            #pragma unroll
            for (int h = 0; h < 8; h++){
                float s = warpReduceSum(acc[h]);
                if (lane == h)
                    g_w[(size_t)(b*NH+h)*SQ + key] =
                        (mk == 0) ? -1e9f : (s + sh[8192 + h]) * SCALE;
            }
        }
    }
    gsync();

    // ------- P5: softmax + threshold + renorm -------------------------------
    for (int r = blk; r < NR; r += G){
        float v[8];
        #pragma unroll
        for (int k = 0; k < 8; k++) v[k] = g_w[(size_t)r*SQ + tid + k*256];

        float m = v[0];
        #pragma unroll
        for (int k = 1; k < 8; k++) m = fmaxf(m, v[k]);
        m = warpReduceMax(m);
        if (lane == 0) sh[warp] = m;
        __syncthreads();
        float mx = sh[0];
        #pragma unroll
        for (int k = 1; k < 8; k++) mx = fmaxf(mx, sh[k]);
        __syncthreads();

        float p[8], ls = 0.f;
        #pragma unroll
        for (int k = 0; k < 8; k++){ p[k] = expf(v[k]-mx); ls += p[k]; }
        ls = warpReduceSum(ls);
        if (lane == 0) sh[warp] = ls;
        __syncthreads();
        float denom = 0.f;
        #pragma unroll
        for (int k = 0; k < 8; k++) denom += sh[k];
        __syncthreads();

        float inv_d = 1.f/denom, ls2 = 0.f;
        #pragma unroll
        for (int k = 0; k < 8; k++){
            float w0 = p[k]*inv_d;
            p[k] = (w0 < 0.001f) ? 0.f : w0;
            ls2 += p[k];
        }
        ls2 = warpReduceSum(ls2);
        if (lane == 0) sh[warp] = ls2;
        __syncthreads();
        float s2 = 0.f;
        #pragma unroll
        for (int k = 0; k < 8; k++) s2 += sh[k];
        float inv2 = 1.f/(s2 + 1e-9f);

        #pragma unroll
        for (int k = 0; k < 8; k++){
            float wf = p[k]*inv2;
            int key = tid + k*256;
            g_w[(size_t)r*SQ + key] = wf;
            if (wout) wout[(size_t)r*SQ + key] = wf;
        }
        if (tid == 0) g_wsum[r] = s2*inv2;
        __syncthreads();
    }
    gsync();

    // ------- P6: u[r,i] += sum_key w * x (sparse; X in L2) ------------------
    {
        int b = blk & 3, q = blk >> 2, Q = G >> 2;
        float4 acc[8];
        #pragma unroll
        for (int h = 0; h < 8; h++) acc[h] = make_float4(0.f,0.f,0.f,0.f);
        const float4* Xb4 = (const float4*)(X + (size_t)b*SQ*HD);
        bool did = false;
        for (int kg = q; kg < SQ/32; kg += Q){
            int k0 = kg*32;
            {   int h = tid >> 5, kk = tid & 31;
                sh[tid] = g_w[(size_t)(b*NH+h)*SQ + k0 + kk]; }
            __syncthreads();
            for (int kk = 0; kk < 32; kk++){
                float wv[8];
                bool nz = false;
                #pragma unroll
                for (int h = 0; h < 8; h++){ wv[h] = sh[h*32 + kk]; nz |= (wv[h] != 0.f); }
                if (nz){
                    float4 x = Xb4[(size_t)(k0+kk)*256 + tid];
                    #pragma unroll
                    for (int h = 0; h < 8; h++){
                        acc[h].x += wv[h]*x.x; acc[h].y += wv[h]*x.y;
                        acc[h].z += wv[h]*x.z; acc[h].w += wv[h]*x.w;
                    }
                }
            }
            did = true;
            __syncthreads();
        }
        if (did){
            #pragma unroll
            for (int h = 0; h < 8; h++){
                float* up = &g_u[(size_t)(b*NH+h)*HD + tid*4];
                atomicAdd(up+0, acc[h].x);
                atomicAdd(up+1, acc[h].y);
                atomicAdd(up+2, acc[h].z);
                atomicAdd(up+3, acc[h].w);
            }
        }
    }
    gsync();

    // ------- P7: z[r,i] = Wv[i,:] . u[r,:] + bv[i]*wsum[r] ------------------
    {
        int b = blk & 3, q = blk >> 2, Q = G >> 2;
        for (int idx = tid; idx < NH*HD; idx += T)
            sh[idx] = g_u[(size_t)(b*NH)*HD + idx];
        if (tid < NH) sh[8192 + tid] = g_wsum[b*NH + tid];
        __syncthreads();
        const float4* sh4 = (const float4*)sh;
        for (int i = q*8 + warp; i < HD; i += Q*8){
            const float4* w4 = (const float4*)(Wv + (size_t)i*HD);
            float acc[8];
            #pragma unroll
            for (int h = 0; h < 8; h++) acc[h] = 0.f;
            #pragma unroll
            for (int c = 0; c < 8; c++){
                float4 wr = w4[c*32 + lane];
                #pragma unroll
                for (int h = 0; h < 8; h++)
                    acc[h] += dot4(wr, sh4[h*256 + c*32 + lane]);
            }
            float bvi = bv[i];
            #pragma unroll
            for (int h = 0; h < 8; h++){
                float s = warpReduceSum(acc[h]);
                if (lane == h)
                    g_z[(size_t)(b*NH+h)*HD + i] = s + bvi*sh[8192 + h];
            }
        }
    }
    gsync();

    // ------- P8: attn0 = wiv . z + biv*wsum ---------------------------------
    for (int o = gw; o < NB*HD; o += NWd){
        int b = o >> 10, hj = o & (HD-1), h = hj >> 7;
        float v = warpDot1024(ipw + (size_t)(2*HD + hj)*HD,
                              g_z + (size_t)(b*NH + h)*HD);
        if (lane == 0) g_attn0[o] = v + ipb[2*HD + hj]*g_wsum[b*NH + h];
    }
    gsync();

    // ------- P9: res = opw . attn0 + opb + x0 -------------------------------
    for (int o = gw; o < NB*HD; o += NWd){
        int b = o >> 10, i = o & (HD-1);
        float v = warpDot1024(opw + (size_t)i*HD, g_attn0 + (size_t)b*HD);
        if (lane == 0) g_res[o] = v + opb[i] + X[(size_t)b*SQ*HD + i];
    }
    gsync();

    // ------- P10+P11 fused: per-block LN into smem, then logits -------------
    {
        const float4* lg4 = (const float4*)lng;
        const float4* lb4 = (const float4*)lnb;
        for (int b = 0; b < NB; b++){
            float4 v = ((const float4*)(g_res + (size_t)b*HD))[tid];
            float s  = v.x + v.y + v.z + v.w;
            float qq = v.x*v.x + v.y*v.y + v.z*v.z + v.w*v.w;
            s  = warpReduceSum(s);
            qq = warpReduceSum(qq);
            __syncthreads();
            if (lane == 0){ sh[4096 + warp] = s; sh[4104 + warp] = qq; }
            __syncthreads();
            float S = 0.f, Q2 = 0.f;
            #pragma unroll
            for (int k = 0; k < 8; k++){ S += sh[4096 + k]; Q2 += sh[4104 + k]; }
            float mu  = S * (1.f/HD);
            float var = Q2 * (1.f/HD) - mu*mu;
            float inv = rsqrtf(var + 1e-5f);
            float4 g = lg4[tid], bb = lb4[tid];
            float4 o;
            o.x = (v.x - mu)*inv*g.x + bb.x;
            o.y = (v.y - mu)*inv*g.y + bb.y;
            o.z = (v.z - mu)*inv*g.z + bb.z;
            o.w = (v.w - mu)*inv*g.w + bb.w;
            ((float4*)sh)[b*256 + tid] = o;
        }
        __syncthreads();
        const float4* cls4 = (const float4*)sh;
        for (int o = gw; o < NB*NC; o += NWd){
            int b = o / NC, c = o % NC;
            const float4* w4 = (const float4*)(fcw + (size_t)c*HD);
            float acc = 0.f;
            #pragma unroll
            for (int k = 0; k < 8; k++)
                acc += dot4(w4[lane + 32*k], cls4[b*256 + lane + 32*k]);
            acc = warpReduceSum(acc);
            if (lane == 0) out[o] = acc + fcb[c];
        }
    }
}

// ---------------------------------------------------------------------------
extern "C" void kernel_launch(void* const* d_in, const int* in_sizes, int n_in,
                              void* d_out, int out_size){
    const float* X    = (const float*)d_in[0];
    const int*   mask = (const int*)  d_in[1];
    const float* Wq   = (const float*)d_in[2];
    const float* bq   = (const float*)d_in[3];
    const float* Wk   = (const float*)d_in[4];
    const float* bk   = (const float*)d_in[5];
    const float* Wv   = (const float*)d_in[6];
    const float* bv   = (const float*)d_in[7];
    const float* ipw  = (const float*)d_in[8];
    const float* ipb  = (const float*)d_in[9];
    const float* opw  = (const float*)d_in[10];
    const float* opb  = (const float*)d_in[11];
    const float* lng  = (const float*)d_in[12];
    const float* lnb  = (const float*)d_in[13];
    const float* fcw  = (const float*)d_in[14];
    const float* fcb  = (const float*)d_in[15];
    float* out  = (float*)d_out;
    float* wout = (out_size >= NB*NC + NR*SQ) ? (out + NB*NC) : nullptr;

    int dev = 0;
    cudaGetDevice(&dev);
    int sms = 0;
    cudaDeviceGetAttribute(&sms, cudaDevAttrMultiProcessorCount, dev);
    if (sms < 8) sms = 132;
    int G = sms & ~3;

    fused_kernel<<<G, T>>>(X, mask, Wq, bq, Wk, bk, Wv, bv,
                           ipw, ipb, opw, opb, lng, lnb, fcw, fcb,
                           out, wout);
}

// round 7
// speedup vs baseline: 1.6942x; 1.6942x over previous
#include <cuda_runtime.h>
#include <math.h>

#define G   132
#define T   256
#define NW  (G*8)
#define NB  4
#define SQ  2048
#define HD  1024
#define NH  8
#define NC  1000
#define NR  32

#define SCALE 0.088388347648318433f  // 1/sqrt(128)

// ---------------- scratch (device globals; no allocations allowed) ----------
__device__ unsigned g_barcnt = 0;
__device__ __align__(16) float g_tmpq[NB*HD];
__device__ __align__(16) float g_q0[NB*HD];
__device__ __align__(16) float g_a[NR*HD];
__device__ __align__(16) float g_c0[NR];
__device__ __align__(16) float g_t[NR*HD];
__device__ __align__(16) float g_w[NR*SQ];
__device__ __align__(16) float g_u[NR*HD];
__device__ __align__(16) float g_wsum[NR];
__device__ __align__(16) float g_z[NR*HD];
__device__ __align__(16) float g_attn0[NB*HD];
__device__ __align__(16) float g_res[NB*HD];

__device__ __forceinline__ float warpReduceSum(float v){
    v += __shfl_xor_sync(0xffffffffu, v, 16);
    v += __shfl_xor_sync(0xffffffffu, v, 8);
    v += __shfl_xor_sync(0xffffffffu, v, 4);
    v += __shfl_xor_sync(0xffffffffu, v, 2);
    v += __shfl_xor_sync(0xffffffffu, v, 1);
    return v;
}
__device__ __forceinline__ float warpReduceMax(float v){
    v = fmaxf(v, __shfl_xor_sync(0xffffffffu, v, 16));
    v = fmaxf(v, __shfl_xor_sync(0xffffffffu, v, 8));
    v = fmaxf(v, __shfl_xor_sync(0xffffffffu, v, 4));
    v = fmaxf(v, __shfl_xor_sync(0xffffffffu, v, 2));
    v = fmaxf(v, __shfl_xor_sync(0xffffffffu, v, 1));
    return v;
}
__device__ __forceinline__ float dot4(const float4 a, const float4 b){
    return a.x*b.x + a.y*b.y + a.z*b.z + a.w*b.w;
}

// grid-wide barrier: monotonic counter, TIGHT spin (no nanosleep — its wake
// granularity is hint-only and can cost ~1us per barrier).
__device__ __forceinline__ void gsync(){
    __threadfence();              // release
    __syncthreads();
    if (threadIdx.x == 0){
        unsigned old = atomicAdd(&g_barcnt, 1u);
        unsigned target = (old / G + 1u) * G;
        while (*(volatile unsigned*)&g_barcnt < target){ }
    }
    __syncthreads();
    __threadfence();              // acquire
}

// warp-collective dot of two 1024-float vectors (both global)
__device__ __forceinline__ float warpDot1024(const float* __restrict__ A,
                                             const float* __restrict__ B){
    const float4* a4 = (const float4*)A;
    const float4* b4 = (const float4*)B;
    int lane = threadIdx.x & 31;
    float acc = 0.f;
    #pragma unroll
    for (int k = 0; k < 8; k++)
        acc += dot4(a4[lane + 32*k], b4[lane + 32*k]);
    return warpReduceSum(acc);
}

__global__ __launch_bounds__(T, 2)
void fused_kernel(const float* __restrict__ X,   const int*   __restrict__ mask,
                  const float* __restrict__ Wq,  const float* __restrict__ bq,
                  const float* __restrict__ Wk,  const float* __restrict__ bk,
                  const float* __restrict__ Wv,  const float* __restrict__ bv,
                  const float* __restrict__ ipw, const float* __restrict__ ipb,
                  const float* __restrict__ opw, const float* __restrict__ opb,
                  const float* __restrict__ lng, const float* __restrict__ lnb,
                  const float* __restrict__ fcw, const float* __restrict__ fcb,
                  float* __restrict__ out, float* __restrict__ wout)
{
    __shared__ __align__(16) float sh[8208];
    const int tid  = threadIdx.x;
    const int blk  = blockIdx.x;
    const int lane = tid & 31;
    const int warp = tid >> 5;
    const int gw   = blk*8 + warp;      // global warp id 0..1055

    // ---------------- P0: zero accumulators + tmpq = Wq . x0 + bq ----------
    for (int i = blk*T + tid; i < NR*HD; i += G*T){ g_t[i] = 0.f; g_u[i] = 0.f; }
    for (int o = gw; o < NB*HD; o += NW){
        int b = o >> 10, i = o & (HD-1);
        float v = warpDot1024(Wq + (size_t)i*HD, X + (size_t)b*SQ*HD);
        if (lane == 0) g_tmpq[o] = v + bq[i];
    }
    gsync();

    // ---------------- P1: q0 = wiq . tmpq + biq ----------------------------
    for (int o = gw; o < NB*HD; o += NW){
        int b = o >> 10, i = o & (HD-1);
        float v = warpDot1024(ipw + (size_t)i*HD, g_tmpq + (size_t)b*HD);
        if (lane == 0) g_q0[o] = v + ipb[i];
    }
    gsync();

    // ---------------- P2: a[r,i] = sum_j wik_h[j,i]*q0_h[j] ----------------
    if (blk < 128){
        int r = blk >> 2;                // 0..31, one r per 4 blocks
        int b = r >> 3, h = r & 7;
        int i = (blk & 3)*256 + tid;
        if (tid < 128) sh[tid] = g_q0[b*HD + h*128 + tid];
        __syncthreads();
        const float* wik = ipw + (size_t)(HD + h*128)*HD + i;
        float acc = 0.f;
        #pragma unroll 8
        for (int j = 0; j < 128; j++) acc += wik[(size_t)j*HD] * sh[j];
        g_a[r*HD + i] = acc;
    }
    gsync();

    // ---------------- P3: t += a . Wk (tiled) ; c0 on spare blocks ---------
    if (blk < 128){
        int it = blk >> 4, mc = blk & 15;
        int i0 = it*128, m0 = mc*64;
        for (int idx = tid; idx < NR*64; idx += T){
            int r = idx >> 6, m = idx & 63;
            sh[idx] = g_a[r*HD + m0 + m];
        }
        __syncthreads();
        int tx = tid & 127, ty = tid >> 7;     // ty in {0,1}
        float acc[16];
        #pragma unroll
        for (int q = 0; q < 16; q++) acc[q] = 0.f;
        const float* wk = Wk + (size_t)m0*HD + i0 + tx;
        for (int mm = 0; mm < 64; mm++){
            float wv = wk[(size_t)mm*HD];
            #pragma unroll
            for (int q = 0; q < 16; q++) acc[q] += sh[(ty*16+q)*64 + mm] * wv;
        }
        #pragma unroll
        for (int q = 0; q < 16; q++)
            atomicAdd(&g_t[(size_t)(ty*16+q)*HD + i0 + tx], acc[q]);
    } else {
        int r = (blk - 128)*8 + warp;          // 0..31
        int b = r >> 3, h = r & 7;
        float acc = 0.f;
        for (int i = lane; i < HD; i += 32) acc += g_a[r*HD + i] * bk[i];
        for (int j = lane; j < 128; j += 32)
            acc += g_q0[b*HD + h*128 + j] * ipb[HD + h*128 + j];
        acc = warpReduceSum(acc);
        if (lane == 0) g_c0[r] = acc;
    }
    gsync();

    // ---------------- P4: scores[r,key] = (t . x + c0)*SCALE ---------------
    {
        int b = blk / 33, rem = blk % 33;
        for (int idx = tid; idx < NH*HD; idx += T)
            sh[idx] = g_t[(size_t)(b*NH)*HD + idx];
        if (tid < NH) sh[8192 + tid] = g_c0[b*NH + tid];
        __syncthreads();
        const float4* sh4 = (const float4*)sh;
        int gww = rem*8 + warp;                // 0..263
        for (int key = gww; key < SQ; key += 264){
            const float4* x4 = (const float4*)(X + ((size_t)b*SQ + key)*HD);
            float4 xr[8];
            #pragma unroll
            for (int c = 0; c < 8; c++) xr[c] = x4[c*32 + lane];
            int mk = mask[b*SQ + key];
            #pragma unroll
            for (int h = 0; h < 8; h++){
                float acc = 0.f;
                #pragma unroll
                for (int c = 0; c < 8; c++)
                    acc += dot4(xr[c], sh4[h*256 + c*32 + lane]);
                acc = warpReduceSum(acc);
                if (lane == h)
                    g_w[(size_t)(b*NH+h)*SQ + key] =
                        (mk == 0) ? -1e9f : (acc + sh[8192 + h]) * SCALE;
            }
        }
    }
    gsync();

    // ---------------- P5: softmax + threshold + renorm ---------------------
    if (blk < NR){
        int r = blk;
        float v[8];
        #pragma unroll
        for (int k = 0; k < 8; k++) v[k] = g_w[(size_t)r*SQ + tid + k*256];

        float m = v[0];
        #pragma unroll
        for (int k = 1; k < 8; k++) m = fmaxf(m, v[k]);
        m = warpReduceMax(m);
        if (lane == 0) sh[warp] = m;
        __syncthreads();
        float mx = sh[0];
        #pragma unroll
        for (int k = 1; k < 8; k++) mx = fmaxf(mx, sh[k]);
        __syncthreads();

        float p[8], ls = 0.f;
        #pragma unroll
        for (int k = 0; k < 8; k++){ p[k] = expf(v[k]-mx); ls += p[k]; }
        ls = warpReduceSum(ls);
        if (lane == 0) sh[warp] = ls;
        __syncthreads();
        float denom = 0.f;
        #pragma unroll
        for (int k = 0; k < 8; k++) denom += sh[k];
        __syncthreads();

        float inv_d = 1.f/denom, ls2 = 0.f;
        #pragma unroll
        for (int k = 0; k < 8; k++){
            float w0 = p[k]*inv_d;
            p[k] = (w0 < 0.001f) ? 0.f : w0;
            ls2 += p[k];
        }
        ls2 = warpReduceSum(ls2);
        if (lane == 0) sh[warp] = ls2;
        __syncthreads();
        float s2 = 0.f;
        #pragma unroll
        for (int k = 0; k < 8; k++) s2 += sh[k];
        float inv2 = 1.f/(s2 + 1e-9f);

        #pragma unroll
        for (int k = 0; k < 8; k++){
            float wf = p[k]*inv2;
            int key = tid + k*256;
            g_w[(size_t)r*SQ + key] = wf;
            if (wout) wout[(size_t)r*SQ + key] = wf;
        }
        if (tid == 0) g_wsum[r] = s2*inv2;
    }
    gsync();

    // ---------------- P6: u[r,i] += sum_key w * x (sparse) -----------------
    {
        int b = blk / 33, rem = blk % 33;
        int k0  = rem*62 + (rem < 2 ? rem : 2);
        int cnt = 62 + (rem < 2 ? 1 : 0);
        for (int idx = tid; idx < 8*63; idx += T){
            int h = idx / 63, kk = idx - h*63;
            if (kk < cnt) sh[idx] = g_w[(size_t)(b*NH+h)*SQ + k0 + kk];
        }
        __syncthreads();
        float4 acc[8];
        #pragma unroll
        for (int h = 0; h < 8; h++) acc[h] = make_float4(0.f,0.f,0.f,0.f);
        const float4* Xb4 = (const float4*)(X + (size_t)b*SQ*HD);
        for (int kk = 0; kk < cnt; kk++){
            float wv[8];
            bool nz = false;
            #pragma unroll
            for (int h = 0; h < 8; h++){ wv[h] = sh[h*63 + kk]; nz |= (wv[h] != 0.f); }
            if (nz){
                float4 x = Xb4[(size_t)(k0+kk)*256 + tid];
                #pragma unroll
                for (int h = 0; h < 8; h++){
                    acc[h].x += wv[h]*x.x; acc[h].y += wv[h]*x.y;
                    acc[h].z += wv[h]*x.z; acc[h].w += wv[h]*x.w;
                }
            }
        }
        #pragma unroll
        for (int h = 0; h < 8; h++){
            float* up = &g_u[(size_t)(b*NH+h)*HD + tid*4];
            atomicAdd(up+0, acc[h].x);
            atomicAdd(up+1, acc[h].y);
            atomicAdd(up+2, acc[h].z);
            atomicAdd(up+3, acc[h].w);
        }
    }
    gsync();

    // ---------------- P7: z[r,i] = Wv[i,:] . u[r,:] + bv[i]*wsum[r] --------
    {
        int b = blk / 33, rem = blk % 33;
        for (int idx = tid; idx < NH*HD; idx += T)
            sh[idx] = g_u[(size_t)(b*NH)*HD + idx];
        if (tid < NH) sh[8192 + tid] = g_wsum[b*NH + tid];
        __syncthreads();
        const float4* sh4 = (const float4*)sh;
        int gww = rem*8 + warp;
        for (int i = gww; i < HD; i += 264){
            const float4* wv4 = (const float4*)(Wv + (size_t)i*HD);
            float4 wr[8];
            #pragma unroll
            for (int c = 0; c < 8; c++) wr[c] = wv4[c*32 + lane];
            #pragma unroll
            for (int h = 0; h < 8; h++){
                float acc = 0.f;
                #pragma unroll
                for (int c = 0; c < 8; c++)
                    acc += dot4(wr[c], sh4[h*256 + c*32 + lane]);
                acc = warpReduceSum(acc);
                if (lane == h)
                    g_z[(size_t)(b*NH+h)*HD + i] = acc + bv[i]*sh[8192 + h];
            }
        }
    }
    gsync();

    // ---------------- P8: attn0 = wiv . z + biv*wsum -----------------------
    for (int o = gw; o < NB*HD; o += NW){
        int b = o >> 10, hj = o & (HD-1), h = hj >> 7;
        float v = warpDot1024(ipw + (size_t)(2*HD + hj)*HD,
                              g_z + (size_t)(b*NH + h)*HD);
        if (lane == 0) g_attn0[o] = v + ipb[2*HD + hj]*g_wsum[b*NH + h];
    }
    gsync();

    // ---------------- P9: res = opw . attn0 + opb + x0 ---------------------
    for (int o = gw; o < NB*HD; o += NW){
        int b = o >> 10, i = o & (HD-1);
        float v = warpDot1024(opw + (size_t)i*HD, g_attn0 + (size_t)b*HD);
        if (lane == 0) g_res[o] = v + opb[i] + X[(size_t)b*SQ*HD + i];
    }
    gsync();

    // ---------------- P10+P11 fused: per-block LN to smem, then logits -----
    {
        const float4* lg4 = (const float4*)lng;
        const float4* lb4 = (const float4*)lnb;
        for (int b = 0; b < NB; b++){
            float4 v = ((const float4*)(g_res + (size_t)b*HD))[tid];
            float s  = v.x + v.y + v.z + v.w;
            float qq = v.x*v.x + v.y*v.y + v.z*v.z + v.w*v.w;
            s  = warpReduceSum(s);
            qq = warpReduceSum(qq);
            __syncthreads();
            if (lane == 0){ sh[4096 + warp] = s; sh[4104 + warp] = qq; }
            __syncthreads();
            float S = 0.f, Q2 = 0.f;
            #pragma unroll
            for (int k = 0; k < 8; k++){ S += sh[4096 + k]; Q2 += sh[4104 + k]; }
            float mu  = S * (1.f/HD);
            float var = Q2 * (1.f/HD) - mu*mu;
            float inv = rsqrtf(var + 1e-5f);
            float4 g = lg4[tid], bb = lb4[tid];
            float4 o;
            o.x = (v.x - mu)*inv*g.x + bb.x;
            o.y = (v.y - mu)*inv*g.y + bb.y;
            o.z = (v.z - mu)*inv*g.z + bb.z;
            o.w = (v.w - mu)*inv*g.w + bb.w;
            ((float4*)sh)[b*256 + tid] = o;
        }
        __syncthreads();
        const float4* cls4 = (const float4*)sh;
        for (int o = gw; o < NB*NC; o += NW){
            int b = o / NC, c = o % NC;
            const float4* w4 = (const float4*)(fcw + (size_t)c*HD);
            float acc = 0.f;
            #pragma unroll
            for (int k = 0; k < 8; k++)
                acc += dot4(w4[lane + 32*k], cls4[b*256 + lane + 32*k]);
            acc = warpReduceSum(acc);
            if (lane == 0) out[o] = acc + fcb[c];
        }
    }
}

// ---------------------------------------------------------------------------
extern "C" void kernel_launch(void* const* d_in, const int* in_sizes, int n_in,
                              void* d_out, int out_size){
    const float* X    = (const float*)d_in[0];
    const int*   mask = (const int*)  d_in[1];
    const float* Wq   = (const float*)d_in[2];
    const float* bq   = (const float*)d_in[3];
    const float* Wk   = (const float*)d_in[4];
    const float* bk   = (const float*)d_in[5];
    const float* Wv   = (const float*)d_in[6];
    const float* bv   = (const float*)d_in[7];
    const float* ipw  = (const float*)d_in[8];
    const float* ipb  = (const float*)d_in[9];
    const float* opw  = (const float*)d_in[10];
    const float* opb  = (const float*)d_in[11];
    const float* lng  = (const float*)d_in[12];
    const float* lnb  = (const float*)d_in[13];
    const float* fcw  = (const float*)d_in[14];
    const float* fcb  = (const float*)d_in[15];
    float* out  = (float*)d_out;
    float* wout = (out_size >= NB*NC + NR*SQ) ? (out + NB*NC) : nullptr;

    fused_kernel<<<G, T>>>(X, mask, Wq, bq, Wk, bk, Wv, bv,
                           ipw, ipb, opw, opb, lng, lnb, fcw, fcb,
                           out, wout);
}